// round 15
// baseline (speedup 1.0000x reference)
#include <cuda_runtime.h>
#include <math.h>

#define NCB   64
#define CDIM  256
#define DDIM  64
#define KDIM  32
#define ALPHA 8
#define HDIM  256
#define MODI  225   // K + 3D + 1
#define MODO  97    // K + 1 + D

// Fast transcendentals via MUFU.EX2 / MUFU.RCP (rel err ~1e-6, budget 1e-3)
__device__ __forceinline__ float sigm(float x) {
    return __fdividef(1.0f, 1.0f + __expf(-x));
}
__device__ __forceinline__ float ftanh(float x) {
    return 1.0f - __fdividef(2.0f, __expf(2.0f * x) + 1.0f);
}

// packed f32x2 helpers
__device__ __forceinline__ unsigned long long pk(float x, float y) {
    unsigned long long u;
    asm("mov.b64 %0, {%1, %2};" : "=l"(u) : "f"(x), "f"(y));
    return u;
}
__device__ __forceinline__ unsigned long long ffma2u(unsigned long long a, unsigned long long b, unsigned long long c) {
    unsigned long long d;
    asm("fma.rn.f32x2 %0, %1, %2, %3;" : "=l"(d) : "l"(a), "l"(b), "l"(c));
    return d;
}
__device__ __forceinline__ float2 upk(unsigned long long u) {
    float lo, hi;
    asm("mov.b64 {%0, %1}, %2;" : "=f"(lo), "=f"(hi) : "l"(u));
    return make_float2(lo, hi);
}

// float4-interleaved transposed weights
__device__ float g_sw1T4[48 * 256 * 4];
__device__ float g_mw1T4[48 * 256 * 4];
__device__ float g_sw1last[256];
__device__ float g_sw2T4[64 * 64 * 4];
__device__ float g_mw2T4[64 * 64 * 4];

// Partial means scratch: 512 half-bn blocks
__device__ float g_ph [512 * 64];
__device__ float g_pp [512 * 64];
__device__ float g_phb[512 * 32];
__device__ float g_pd [512];
__device__ float g_pmg[512];

// mod MLP layer-2 partials
__device__ float g_l2p[256 * 4 * 100];

// per-nc neuron_id dots: [nc][hh][c] c-minor
__device__ float g_ndot_s[64 * 256 * 8];
__device__ float g_ndot_m[64 * 256 * 8];

#define MEANS_BLOCKS 512
#define PREP_BLOCKS  129

// ---------------- K1 ----------------
__global__ __launch_bounds__(256)
void means_prep_kernel(const float* __restrict__ h,
                       const float* __restrict__ primitives_state,
                       const float* __restrict__ hebbian_traces,
                       const float* __restrict__ decay_logit,
                       const float* __restrict__ msg_magnitude,
                       const float* __restrict__ sw1,
                       const float* __restrict__ mw1,
                       const float* __restrict__ sw2,
                       const float* __restrict__ mw2)
{
    const int tid = threadIdx.x;

    if (blockIdx.x >= MEANS_BLOCKS) {
        int pt = (blockIdx.x - MEANS_BLOCKS) * 256 + tid;
        if (pt < 12288) {
            int i4 = pt >> 8, hh = pt & 255;
            float4 v = make_float4(sw1[hh * 193 + i4 * 4 + 0], sw1[hh * 193 + i4 * 4 + 1],
                                   sw1[hh * 193 + i4 * 4 + 2], sw1[hh * 193 + i4 * 4 + 3]);
            *(float4*)&g_sw1T4[pt * 4] = v;
        } else if (pt < 24576) {
            int q = pt - 12288, i4 = q >> 8, hh = q & 255;
            float4 v = make_float4(mw1[hh * 192 + i4 * 4 + 0], mw1[hh * 192 + i4 * 4 + 1],
                                   mw1[hh * 192 + i4 * 4 + 2], mw1[hh * 192 + i4 * 4 + 3]);
            *(float4*)&g_mw1T4[q * 4] = v;
        } else if (pt < 28672) {
            int q = pt - 24576, h4 = q >> 6, d = q & 63;
            float4 v = make_float4(sw2[d * 256 + h4 * 4 + 0], sw2[d * 256 + h4 * 4 + 1],
                                   sw2[d * 256 + h4 * 4 + 2], sw2[d * 256 + h4 * 4 + 3]);
            *(float4*)&g_sw2T4[q * 4] = v;
        } else if (pt < 32768) {
            int q = pt - 28672, h4 = q >> 6, d = q & 63;
            float4 v = make_float4(mw2[d * 256 + h4 * 4 + 0], mw2[d * 256 + h4 * 4 + 1],
                                   mw2[d * 256 + h4 * 4 + 2], mw2[d * 256 + h4 * 4 + 3]);
            *(float4*)&g_mw2T4[q * 4] = v;
        } else if (pt < 33024) {
            int hh = pt - 32768;
            g_sw1last[hh] = sw1[hh * 193 + 192];
        }
        return;
    }

    __shared__ float s_h[1024];
    __shared__ float s_p[1024];
    __shared__ float s_b[1024];

    const int bn   = blockIdx.x >> 1;
    const int half = blockIdx.x & 1;
    const int c0   = half * 128;
    const int lane = tid & 31;
    const int warp = tid >> 5;
    const int pidx = blockIdx.x;

    const float4* hp4 = (const float4*)(h                + (long)bn * CDIM * DDIM + (long)c0 * DDIM);
    const float4* pp4 = (const float4*)(primitives_state + (long)bn * CDIM * DDIM + (long)c0 * DDIM);
    const float4* hb4 = (const float4*)(hebbian_traces   + (long)bn * CDIM * KDIM + (long)c0 * KDIM);

    const int v16 = tid & 15;
    const int cgr = tid >> 4;
    const int v8  = tid & 7;
    const int cb  = tid >> 3;

    float4 ha[8], pa[8], ba[4];
    #pragma unroll
    for (int j = 0; j < 8; j++) ha[j] = hp4[(cgr + 16 * j) * 16 + v16];
    #pragma unroll
    for (int j = 0; j < 8; j++) pa[j] = pp4[(cgr + 16 * j) * 16 + v16];
    #pragma unroll
    for (int j = 0; j < 4; j++) ba[j] = hb4[(cb + 32 * j) * 8 + v8];

    if (warp == 0) {
        const float* dl = decay_logit + (long)bn * CDIM + c0;
        float v = dl[lane] + dl[lane + 32] + dl[lane + 64] + dl[lane + 96];
        #pragma unroll
        for (int off = 16; off; off >>= 1) v += __shfl_down_sync(0xffffffffu, v, off);
        if (lane == 0) g_pd[pidx] = v;
    } else if (warp == 1) {
        const float* mg = msg_magnitude + (long)bn * CDIM + c0;
        float v = mg[lane] + mg[lane + 32] + mg[lane + 64] + mg[lane + 96];
        #pragma unroll
        for (int off = 16; off; off >>= 1) v += __shfl_down_sync(0xffffffffu, v, off);
        if (lane == 0) g_pmg[pidx] = v;
    }

    float4 hs, ps, bs;
    hs.x = ((ha[0].x + ha[1].x) + (ha[2].x + ha[3].x)) + ((ha[4].x + ha[5].x) + (ha[6].x + ha[7].x));
    hs.y = ((ha[0].y + ha[1].y) + (ha[2].y + ha[3].y)) + ((ha[4].y + ha[5].y) + (ha[6].y + ha[7].y));
    hs.z = ((ha[0].z + ha[1].z) + (ha[2].z + ha[3].z)) + ((ha[4].z + ha[5].z) + (ha[6].z + ha[7].z));
    hs.w = ((ha[0].w + ha[1].w) + (ha[2].w + ha[3].w)) + ((ha[4].w + ha[5].w) + (ha[6].w + ha[7].w));
    ps.x = ((pa[0].x + pa[1].x) + (pa[2].x + pa[3].x)) + ((pa[4].x + pa[5].x) + (pa[6].x + pa[7].x));
    ps.y = ((pa[0].y + pa[1].y) + (pa[2].y + pa[3].y)) + ((pa[4].y + pa[5].y) + (pa[6].y + pa[7].y));
    ps.z = ((pa[0].z + pa[1].z) + (pa[2].z + pa[3].z)) + ((pa[4].z + pa[5].z) + (pa[6].z + pa[7].z));
    ps.w = ((pa[0].w + pa[1].w) + (pa[2].w + pa[3].w)) + ((pa[4].w + pa[5].w) + (pa[6].w + pa[7].w));
    bs.x = (ba[0].x + ba[1].x) + (ba[2].x + ba[3].x);
    bs.y = (ba[0].y + ba[1].y) + (ba[2].y + ba[3].y);
    bs.z = (ba[0].z + ba[1].z) + (ba[2].z + ba[3].z);
    bs.w = (ba[0].w + ba[1].w) + (ba[2].w + ba[3].w);

    *(float4*)&s_h[cgr * 64 + v16 * 4] = hs;
    *(float4*)&s_p[cgr * 64 + v16 * 4] = ps;
    *(float4*)&s_b[cb * 32 + v8 * 4]   = bs;
    __syncthreads();

    if (tid < 64) {
        float t = 0.f;
        #pragma unroll
        for (int g = 0; g < 16; g++) t += s_h[g * 64 + tid];
        g_ph[pidx * 64 + tid] = t;
    } else if (tid < 128) {
        int d = tid - 64;
        float t = 0.f;
        #pragma unroll
        for (int g = 0; g < 16; g++) t += s_p[g * 64 + d];
        g_pp[pidx * 64 + d] = t;
    } else if (tid < 160) {
        int k = tid - 128;
        float t = 0.f;
        #pragma unroll
        for (int c2 = 0; c2 < 32; c2++) t += s_b[c2 * 32 + k];
        g_phb[pidx * 32 + k] = t;
    }
}

// ---------------- K2 (unchanged; PDL on K1) ----------------
__global__ __launch_bounds__(256)
void modmlp_kernel(const float* __restrict__ mod_w1,
                   const float* __restrict__ mod_b1,
                   const float* __restrict__ mod_w2,
                   const float* __restrict__ mod_b2,
                   const float* __restrict__ neuron_id)
{
    __shared__ float s_min[2][232];
    __shared__ float s_hid[2][64];
    __shared__ float s_mm[2];
    __shared__ __align__(16) float s_nid[8][64];
    __shared__ float s_ps[4][512];
    __shared__ float s_pm[4][512];

    const int tid  = threadIdx.x;
    const int warp = tid >> 5;
    const int lane = tid & 31;
    const int nc   = blockIdx.x & 63;
    const int q    = (blockIdx.x >> 6) & 3;
    const int bp   = blockIdx.x >> 8;
    const float inv = 1.0f / CDIM;

    if (bp == 0) {
        int c = tid >> 5, d0 = (tid & 31) * 2;
        *(float2*)&s_nid[c][d0] = *(const float2*)&neuron_id[((long)nc * CDIM + (CDIM - ALPHA) + c) * DDIM + d0];
    }

    cudaGridDependencySynchronize();

    {
        int b2 = tid >> 7, r = tid & 127;
        int b  = bp * 2 + b2;
        int p0 = ((b * NCB + nc) << 1);
        if (r < 64) {
            s_min[b2][32 + r] = (g_ph[p0 * 64 + r] + g_ph[(p0 + 1) * 64 + r]) * inv;
        } else {
            int d = r - 64;
            s_min[b2][97 + d] = (g_pp[p0 * 64 + d] + g_pp[(p0 + 1) * 64 + d]) * inv;
        }
        if (tid < 64) {
            int bb = tid >> 5, k = tid & 31;
            int p = (((bp * 2 + bb) * NCB + nc) << 1);
            s_min[bb][k] = (g_phb[p * 32 + k] + g_phb[(p + 1) * 32 + k]) * inv;
        } else if (tid < 66) {
            int bb = tid - 64;
            int p = (((bp * 2 + bb) * NCB + nc) << 1);
            s_min[bb][96] = (g_pd[p] + g_pd[p + 1]) * inv;
        } else if (tid < 68) {
            int bb = tid - 66;
            int p = (((bp * 2 + bb) * NCB + nc) << 1);
            s_mm[bb] = (g_pmg[p] + g_pmg[p + 1]) * inv;
        }
    }
    __syncthreads();
    {
        int b2 = tid >> 7, r = tid & 127;
        if (r < 64) s_min[b2][161 + r] = s_mm[b2];
    }
    __syncthreads();

    if (bp == 0) {
        int hhl = tid & 63, ig = tid >> 6;
        int hh = q * 64 + hhl;
        float accs[8], accm[8];
        #pragma unroll
        for (int c = 0; c < 8; c++) { accs[c] = 0.f; accm[c] = 0.f; }
        #pragma unroll
        for (int s = 0; s < 4; s++) {
            int i4 = 32 + ig * 4 + s;
            int i  = (i4 - 32) * 4;
            float4 ws = *(const float4*)&g_sw1T4[(i4 * 256 + hh) * 4];
            float4 wm = *(const float4*)&g_mw1T4[(i4 * 256 + hh) * 4];
            #pragma unroll
            for (int c = 0; c < 8; c++) {
                float4 nv = *(const float4*)&s_nid[c][i];
                accs[c] += nv.x * ws.x + nv.y * ws.y + nv.z * ws.z + nv.w * ws.w;
                accm[c] += nv.x * wm.x + nv.y * wm.y + nv.z * wm.z + nv.w * wm.w;
            }
        }
        #pragma unroll
        for (int c = 0; c < 8; c++) {
            s_ps[ig][hhl * 8 + c] = accs[c];
            s_pm[ig][hhl * 8 + c] = accm[c];
        }
        __syncthreads();
        for (int o = tid; o < 512; o += 256) {
            int hhl2 = o >> 3;
            int hh2 = q * 64 + hhl2;
            int c = o & 7;
            g_ndot_s[((long)nc * 256 + hh2) * 8 + c] = s_ps[0][o] + s_ps[1][o] + s_ps[2][o] + s_ps[3][o];
            g_ndot_m[((long)nc * 256 + hh2) * 8 + c] = s_pm[0][o] + s_pm[1][o] + s_pm[2][o] + s_pm[3][o];
        }
    }

    for (int r = 0; r < 8; r++) {
        int rloc = warp * 8 + r;
        int h0 = q * 64 + rloc;
        const float* row = mod_w1 + ((long)nc * HDIM + h0) * MODI;
        float a0 = 0.f, a1 = 0.f;
        #pragma unroll
        for (int j = 0; j < 7; j++) {
            int i = lane + 32 * j;
            float w = row[i];
            a0 += w * s_min[0][i];
            a1 += w * s_min[1][i];
        }
        if (lane == 0) {
            float w = row[224];
            a0 += w * s_min[0][224];
            a1 += w * s_min[1][224];
        }
        #pragma unroll
        for (int off = 16; off; off >>= 1) {
            a0 += __shfl_down_sync(0xffffffffu, a0, off);
            a1 += __shfl_down_sync(0xffffffffu, a1, off);
        }
        if (lane == 0) {
            float bias = mod_b1[nc * HDIM + h0];
            s_hid[0][rloc] = ftanh(a0 + bias);
            s_hid[1][rloc] = ftanh(a1 + bias);
        }
    }
    __syncthreads();

    if (tid < 194) {
        int o = tid >> 1, bl = tid & 1;
        int b = bp * 2 + bl;
        const float* w2c = mod_w2 + (long)nc * HDIM * MODO + (long)(q * 64) * MODO + o;
        float a = 0.f;
        #pragma unroll 8
        for (int hh = 0; hh < 64; hh++) a += w2c[hh * MODO] * s_hid[bl][hh];
        if (q == 0) a += mod_b2[nc * MODO + o];
        g_l2p[(((long)b * NCB + nc) * 4 + q) * 100 + o] = a;
    }
}

// ---------------- K3: 2 batches per block; grid 128 = (nc x 2 b-pairs); PDL on K2 ----------------
__global__ __launch_bounds__(256, 2)
void cellmem_kernel(
    const float* __restrict__ h,
    const float* __restrict__ prev_messages,
    const float* __restrict__ state_b1,
    const float* __restrict__ state_b2,
    const float* __restrict__ msg_b1,
    const float* __restrict__ msg_b2,
    const int*   __restrict__ conn_indices,
    float* __restrict__ out)
{
    __shared__ float s_wsig[2][32];
    __shared__ __align__(16) float s_prim[2][64];
    __shared__ float s_scal[2][2];
    __shared__ int   s_conn[256];
    __shared__ __align__(16) float s_hvT[2][512];
    __shared__ __align__(16) float s_invT[2][512];
    __shared__ __align__(16) float s_hnewT[2][512];
    __shared__ __align__(16) float s_scratch[2][2048];
    __shared__ __align__(16) float s_t[2][2048];
    __shared__ __align__(16) float s_acc8T[2][512];

    const int tid  = threadIdx.x;
    const int warp = tid >> 5;
    const int lane = tid & 31;
    const int nc   = blockIdx.x & 63;
    const int bp   = blockIdx.x >> 6;   // 0..1
    const long bn0 = (long)(bp * 2) * NCB + nc;
    const long bn1 = bn0 + NCB;

    // ---- PDL prologue: inputs only ----
    {
        int cc = tid >> 5, k = tid & 31;
        s_conn[tid] = conn_indices[((long)nc * CDIM + (CDIM - ALPHA) + cc) * KDIM + k];
    }
    #pragma unroll
    for (int r = 0; r < 4; r++) {
        int idx = tid + 256 * r;          // 0..1023
        int bb = idx >> 9, li = idx & 511;
        int c = li >> 6, d = li & 63;
        long bnx = bb ? bn1 : bn0;
        s_hvT[bb][d * 8 + c] = h[(bnx * CDIM + (CDIM - ALPHA) + c) * DDIM + d];
    }

    cudaGridDependencySynchronize();

    // ---------- P1 ----------
    if (tid < 194) {
        int bb = tid >= 97, o = bb ? tid - 97 : tid;
        long bnx = bb ? bn1 : bn0;
        float v = g_l2p[(bnx * 4 + 0) * 100 + o] + g_l2p[(bnx * 4 + 1) * 100 + o]
                + g_l2p[(bnx * 4 + 2) * 100 + o] + g_l2p[(bnx * 4 + 3) * 100 + o];
        if (o < KDIM)        s_wsig[bb][o] = sigm(v);
        else if (o == KDIM) { s_scal[bb][0] = v; s_scal[bb][1] = sigm(v); }
        else                 s_prim[bb][o - KDIM - 1] = v;
    }
    __syncthreads();

    // ---------- P5: gather (warp per cell, both batches) ----------
    {
        int cc = warp;
        #pragma unroll
        for (int bb = 0; bb < 2; bb++) {
            const float* pm = prev_messages + (bb ? bn1 : bn0) * CDIM * DDIM;
            float ax = 0.f, ay = 0.f, bx = 0.f, by = 0.f;
            #pragma unroll 4
            for (int k = 0; k < KDIM; k += 2) {
                const float2* p0 = (const float2*)(pm + (long)s_conn[cc * KDIM + k] * DDIM);
                const float2* p1 = (const float2*)(pm + (long)s_conn[cc * KDIM + k + 1] * DDIM);
                float w0 = s_wsig[bb][k], w1 = s_wsig[bb][k + 1];
                float2 v0 = p0[lane], v1 = p1[lane];
                ax += w0 * v0.x; ay += w0 * v0.y;
                bx += w1 * v1.x; by += w1 * v1.y;
            }
            s_invT[bb][(lane * 2) * 8 + cc]     = ax + bx;
            s_invT[bb][(lane * 2 + 1) * 8 + cc] = ay + by;
        }
    }
    __syncthreads();

    // ---------- P6: state hidden (thread = hh, both batches per weight read) ----------
    {
        int hh = tid;
        unsigned long long acc2[2][4];
        {
            const ulonglong2* np = (const ulonglong2*)&g_ndot_s[((long)nc * 256 + hh) * 8];
            ulonglong2 n01 = np[0], n23 = np[1];
            #pragma unroll
            for (int bb = 0; bb < 2; bb++) {
                acc2[bb][0] = n01.x; acc2[bb][1] = n01.y;
                acc2[bb][2] = n23.x; acc2[bb][3] = n23.y;
            }
        }
        float pdot0 = 0.f, pdot1 = 0.f;
        #pragma unroll
        for (int i4 = 0; i4 < 16; i4++) {
            int i = i4 * 4;
            float wa[4], wb[4];
            *(float4*)wa = *(const float4*)&g_sw1T4[(i4 * 256 + hh) * 4];
            *(float4*)wb = *(const float4*)&g_sw1T4[((i4 + 16) * 256 + hh) * 4];
            float4 pv0 = *(const float4*)&s_prim[0][i];
            float4 pv1 = *(const float4*)&s_prim[1][i];
            pdot0 += pv0.x * wb[0] + pv0.y * wb[1] + pv0.z * wb[2] + pv0.w * wb[3];
            pdot1 += pv1.x * wb[0] + pv1.y * wb[1] + pv1.z * wb[2] + pv1.w * wb[3];
            #pragma unroll
            for (int e = 0; e < 4; e++) {
                unsigned long long w2 = pk(wa[e], wa[e]);
                const ulonglong2* iv0 = (const ulonglong2*)&s_invT[0][(i + e) * 8];
                const ulonglong2* iv1 = (const ulonglong2*)&s_invT[1][(i + e) * 8];
                ulonglong2 a01 = iv0[0], a23 = iv0[1];
                ulonglong2 b01 = iv1[0], b23 = iv1[1];
                acc2[0][0] = ffma2u(w2, a01.x, acc2[0][0]);
                acc2[0][1] = ffma2u(w2, a01.y, acc2[0][1]);
                acc2[0][2] = ffma2u(w2, a23.x, acc2[0][2]);
                acc2[0][3] = ffma2u(w2, a23.y, acc2[0][3]);
                acc2[1][0] = ffma2u(w2, b01.x, acc2[1][0]);
                acc2[1][1] = ffma2u(w2, b01.y, acc2[1][1]);
                acc2[1][2] = ffma2u(w2, b23.x, acc2[1][2]);
                acc2[1][3] = ffma2u(w2, b23.y, acc2[1][3]);
            }
        }
        float base = state_b1[hh];
        float sl = g_sw1last[hh];
        float extra0 = pdot0 + base + s_scal[0][0] * sl;
        float extra1 = pdot1 + base + s_scal[1][0] * sl;
        #pragma unroll
        for (int j = 0; j < 4; j++) {
            float2 r0 = upk(acc2[0][j]);
            float2 r1 = upk(acc2[1][j]);
            s_t[0][hh * 8 + 2 * j]     = ftanh(r0.x + extra0);
            s_t[0][hh * 8 + 2 * j + 1] = ftanh(r0.y + extra0);
            s_t[1][hh * 8 + 2 * j]     = ftanh(r1.x + extra1);
            s_t[1][hh * 8 + 2 * j + 1] = ftanh(r1.y + extra1);
        }
    }
    __syncthreads();

    // ---------- P7: update + h_new (thread = (d, hq), both batches per weight read) ----------
    {
        int d = tid & 63, hq = tid >> 6;
        unsigned long long z = pk(0.f, 0.f);
        unsigned long long acc2[2][4] = {{z, z, z, z}, {z, z, z, z}};
        #pragma unroll
        for (int s = 0; s < 16; s++) {
            int h4 = hq * 16 + s, hh = h4 * 4;
            float wa[4];
            *(float4*)wa = *(const float4*)&g_sw2T4[(h4 * 64 + d) * 4];
            #pragma unroll
            for (int e = 0; e < 4; e++) {
                unsigned long long w2 = pk(wa[e], wa[e]);
                const ulonglong2* t0 = (const ulonglong2*)&s_t[0][(hh + e) * 8];
                const ulonglong2* t1 = (const ulonglong2*)&s_t[1][(hh + e) * 8];
                ulonglong2 a01 = t0[0], a23 = t0[1];
                ulonglong2 b01 = t1[0], b23 = t1[1];
                acc2[0][0] = ffma2u(w2, a01.x, acc2[0][0]);
                acc2[0][1] = ffma2u(w2, a01.y, acc2[0][1]);
                acc2[0][2] = ffma2u(w2, a23.x, acc2[0][2]);
                acc2[0][3] = ffma2u(w2, a23.y, acc2[0][3]);
                acc2[1][0] = ffma2u(w2, b01.x, acc2[1][0]);
                acc2[1][1] = ffma2u(w2, b01.y, acc2[1][1]);
                acc2[1][2] = ffma2u(w2, b23.x, acc2[1][2]);
                acc2[1][3] = ffma2u(w2, b23.y, acc2[1][3]);
            }
        }
        #pragma unroll
        for (int bb = 0; bb < 2; bb++) {
            ulonglong2* op = (ulonglong2*)&s_scratch[bb][hq * 512 + d * 8];
            op[0] = make_ulonglong2(acc2[bb][0], acc2[bb][1]);
            op[1] = make_ulonglong2(acc2[bb][2], acc2[bb][3]);
        }
    }
    __syncthreads();
    {
        #pragma unroll
        for (int r = 0; r < 4; r++) {
            int idx = tid + 256 * r;          // 0..1023
            int bb = idx >> 9, li = idx & 511;
            int d = li >> 3;
            float a = s_scratch[bb][li] + s_scratch[bb][512 + li]
                    + s_scratch[bb][1024 + li] + s_scratch[bb][1536 + li]
                    + state_b2[d];
            float ds = s_scal[bb][1];
            s_hnewT[bb][li] = ds * s_hvT[bb][li] + (1.f - ds) * ftanh(a);
        }
    }
    __syncthreads();

    // ---------- P8: msg hidden ----------
    {
        int hh = tid;
        unsigned long long acc2[2][4];
        {
            const ulonglong2* np = (const ulonglong2*)&g_ndot_m[((long)nc * 256 + hh) * 8];
            ulonglong2 n01 = np[0], n23 = np[1];
            #pragma unroll
            for (int bb = 0; bb < 2; bb++) {
                acc2[bb][0] = n01.x; acc2[bb][1] = n01.y;
                acc2[bb][2] = n23.x; acc2[bb][3] = n23.y;
            }
        }
        float pdot0 = 0.f, pdot1 = 0.f;
        #pragma unroll
        for (int i4 = 0; i4 < 16; i4++) {
            int i = i4 * 4;
            float wa[4], wb[4];
            *(float4*)wa = *(const float4*)&g_mw1T4[(i4 * 256 + hh) * 4];
            *(float4*)wb = *(const float4*)&g_mw1T4[((i4 + 16) * 256 + hh) * 4];
            float4 pv0 = *(const float4*)&s_prim[0][i];
            float4 pv1 = *(const float4*)&s_prim[1][i];
            pdot0 += pv0.x * wb[0] + pv0.y * wb[1] + pv0.z * wb[2] + pv0.w * wb[3];
            pdot1 += pv1.x * wb[0] + pv1.y * wb[1] + pv1.z * wb[2] + pv1.w * wb[3];
            #pragma unroll
            for (int e = 0; e < 4; e++) {
                unsigned long long w2 = pk(wa[e], wa[e]);
                const ulonglong2* iv0 = (const ulonglong2*)&s_hnewT[0][(i + e) * 8];
                const ulonglong2* iv1 = (const ulonglong2*)&s_hnewT[1][(i + e) * 8];
                ulonglong2 a01 = iv0[0], a23 = iv0[1];
                ulonglong2 b01 = iv1[0], b23 = iv1[1];
                acc2[0][0] = ffma2u(w2, a01.x, acc2[0][0]);
                acc2[0][1] = ffma2u(w2, a01.y, acc2[0][1]);
                acc2[0][2] = ffma2u(w2, a23.x, acc2[0][2]);
                acc2[0][3] = ffma2u(w2, a23.y, acc2[0][3]);
                acc2[1][0] = ffma2u(w2, b01.x, acc2[1][0]);
                acc2[1][1] = ffma2u(w2, b01.y, acc2[1][1]);
                acc2[1][2] = ffma2u(w2, b23.x, acc2[1][2]);
                acc2[1][3] = ffma2u(w2, b23.y, acc2[1][3]);
            }
        }
        float base = msg_b1[hh];
        float extra0 = pdot0 + base;
        float extra1 = pdot1 + base;
        #pragma unroll
        for (int j = 0; j < 4; j++) {
            float2 r0 = upk(acc2[0][j]);
            float2 r1 = upk(acc2[1][j]);
            s_t[0][hh * 8 + 2 * j]     = ftanh(r0.x + extra0);
            s_t[0][hh * 8 + 2 * j + 1] = ftanh(r0.y + extra0);
            s_t[1][hh * 8 + 2 * j]     = ftanh(r1.x + extra1);
            s_t[1][hh * 8 + 2 * j + 1] = ftanh(r1.y + extra1);
        }
    }
    __syncthreads();

    // ---------- P9: msg out + readout ----------
    {
        int d = tid & 63, hq = tid >> 6;
        unsigned long long z = pk(0.f, 0.f);
        unsigned long long acc2[2][4] = {{z, z, z, z}, {z, z, z, z}};
        #pragma unroll
        for (int s = 0; s < 16; s++) {
            int h4 = hq * 16 + s, hh = h4 * 4;
            float wa[4];
            *(float4*)wa = *(const float4*)&g_mw2T4[(h4 * 64 + d) * 4];
            #pragma unroll
            for (int e = 0; e < 4; e++) {
                unsigned long long w2 = pk(wa[e], wa[e]);
                const ulonglong2* t0 = (const ulonglong2*)&s_t[0][(hh + e) * 8];
                const ulonglong2* t1 = (const ulonglong2*)&s_t[1][(hh + e) * 8];
                ulonglong2 a01 = t0[0], a23 = t0[1];
                ulonglong2 b01 = t1[0], b23 = t1[1];
                acc2[0][0] = ffma2u(w2, a01.x, acc2[0][0]);
                acc2[0][1] = ffma2u(w2, a01.y, acc2[0][1]);
                acc2[0][2] = ffma2u(w2, a23.x, acc2[0][2]);
                acc2[0][3] = ffma2u(w2, a23.y, acc2[0][3]);
                acc2[1][0] = ffma2u(w2, b01.x, acc2[1][0]);
                acc2[1][1] = ffma2u(w2, b01.y, acc2[1][1]);
                acc2[1][2] = ffma2u(w2, b23.x, acc2[1][2]);
                acc2[1][3] = ffma2u(w2, b23.y, acc2[1][3]);
            }
        }
        #pragma unroll
        for (int bb = 0; bb < 2; bb++) {
            ulonglong2* op = (ulonglong2*)&s_scratch[bb][hq * 512 + d * 8];
            op[0] = make_ulonglong2(acc2[bb][0], acc2[bb][1]);
            op[1] = make_ulonglong2(acc2[bb][2], acc2[bb][3]);
        }
    }
    __syncthreads();
    {
        #pragma unroll
        for (int r = 0; r < 4; r++) {
            int idx = tid + 256 * r;
            int bb = idx >> 9, li = idx & 511;
            int d = li >> 3;
            float a = s_scratch[bb][li] + s_scratch[bb][512 + li]
                    + s_scratch[bb][1024 + li] + s_scratch[bb][1536 + li]
                    + msg_b2[d];
            s_acc8T[bb][li] = ftanh(a);
        }
    }
    __syncthreads();
    if (tid < 128) {
        int bb = tid >> 6, d = tid & 63;
        float4 a0 = *(const float4*)&s_acc8T[bb][d * 8];
        float4 a1 = *(const float4*)&s_acc8T[bb][d * 8 + 4];
        int b = bp * 2 + bb;
        out[(long)b * (NCB * DDIM) + nc * DDIM + d] =
            ((a0.x + a0.y) + (a0.z + a0.w) + (a1.x + a1.y) + (a1.z + a1.w)) * 0.125f;
    }
}

extern "C" void kernel_launch(void* const* d_in, const int* in_sizes, int n_in,
                              void* d_out, int out_size)
{
    const float* h          = (const float*)d_in[0];
    const float* prev_msg   = (const float*)d_in[1];
    const float* decay      = (const float*)d_in[2];
    const float* prim       = (const float*)d_in[3];
    const float* hebb       = (const float*)d_in[4];
    const float* msgmag     = (const float*)d_in[5];
    // d_in[6] = cc_signals : dead
    const float* state_w1   = (const float*)d_in[7];
    const float* state_b1   = (const float*)d_in[8];
    const float* state_w2   = (const float*)d_in[9];
    const float* state_b2   = (const float*)d_in[10];
    const float* msg_w1     = (const float*)d_in[11];
    const float* msg_b1     = (const float*)d_in[12];
    const float* msg_w2     = (const float*)d_in[13];
    const float* msg_b2     = (const float*)d_in[14];
    const float* mod_w1     = (const float*)d_in[15];
    const float* mod_b1     = (const float*)d_in[16];
    const float* mod_w2     = (const float*)d_in[17];
    const float* mod_b2     = (const float*)d_in[18];
    const float* neuron_id  = (const float*)d_in[19];
    const int*   conn       = (const int*)d_in[20];
    float* outp             = (float*)d_out;

    means_prep_kernel<<<MEANS_BLOCKS + PREP_BLOCKS, 256>>>(
        h, prim, hebb, decay, msgmag, state_w1, msg_w1, state_w2, msg_w2);

    {
        cudaLaunchConfig_t cfg = {};
        cfg.gridDim  = dim3(512, 1, 1);
        cfg.blockDim = dim3(256, 1, 1);
        cudaLaunchAttribute attrs[1];
        attrs[0].id = cudaLaunchAttributeProgrammaticStreamSerialization;
        attrs[0].val.programmaticStreamSerializationAllowed = 1;
        cfg.attrs = attrs;
        cfg.numAttrs = 1;
        cudaLaunchKernelEx(&cfg, modmlp_kernel, mod_w1, mod_b1, mod_w2, mod_b2, neuron_id);
    }

    {
        cudaLaunchConfig_t cfg = {};
        cfg.gridDim  = dim3(128, 1, 1);
        cfg.blockDim = dim3(256, 1, 1);
        cudaLaunchAttribute attrs[1];
        attrs[0].id = cudaLaunchAttributeProgrammaticStreamSerialization;
        attrs[0].val.programmaticStreamSerializationAllowed = 1;
        cfg.attrs = attrs;
        cfg.numAttrs = 1;
        cudaLaunchKernelEx(&cfg, cellmem_kernel, h, prev_msg,
                           state_b1, state_b2, msg_b1, msg_b2, conn, outp);
    }
}

// round 16
// speedup vs baseline: 1.0098x; 1.0098x over previous
#include <cuda_runtime.h>
#include <math.h>

#define NCB   64
#define CDIM  256
#define DDIM  64
#define KDIM  32
#define ALPHA 8
#define HDIM  256
#define MODI  225   // K + 3D + 1
#define MODO  97    // K + 1 + D

// Fast transcendentals via MUFU.EX2 / MUFU.RCP (rel err ~1e-6, budget 1e-3)
__device__ __forceinline__ float sigm(float x) {
    return __fdividef(1.0f, 1.0f + __expf(-x));
}
__device__ __forceinline__ float ftanh(float x) {
    return 1.0f - __fdividef(2.0f, __expf(2.0f * x) + 1.0f);
}

// packed f32x2 helpers
__device__ __forceinline__ unsigned long long pk(float x, float y) {
    unsigned long long u;
    asm("mov.b64 %0, {%1, %2};" : "=l"(u) : "f"(x), "f"(y));
    return u;
}
__device__ __forceinline__ unsigned long long ffma2u(unsigned long long a, unsigned long long b, unsigned long long c) {
    unsigned long long d;
    asm("fma.rn.f32x2 %0, %1, %2, %3;" : "=l"(d) : "l"(a), "l"(b), "l"(c));
    return d;
}
__device__ __forceinline__ float2 upk(unsigned long long u) {
    float lo, hi;
    asm("mov.b64 {%0, %1}, %2;" : "=f"(lo), "=f"(hi) : "l"(u));
    return make_float2(lo, hi);
}

// float4-interleaved transposed weights
__device__ float g_sw1T4[48 * 256 * 4];
__device__ float g_mw1T4[48 * 256 * 4];
__device__ float g_sw1last[256];
__device__ float g_sw2T4[64 * 64 * 4];
__device__ float g_mw2T4[64 * 64 * 4];

// Partial means scratch: 512 half-bn blocks
__device__ float g_ph [512 * 64];
__device__ float g_pp [512 * 64];
__device__ float g_phb[512 * 32];
__device__ float g_pd [512];
__device__ float g_pmg[512];

// mod MLP layer-2 partials
__device__ float g_l2p[256 * 4 * 100];

// per-nc neuron_id dots: [nc][hh][c] c-minor
__device__ float g_ndot_s[64 * 256 * 8];
__device__ float g_ndot_m[64 * 256 * 8];

#define MEANS_BLOCKS 512
#define PREP_BLOCKS  129

// ---------------- K1 ----------------
__global__ __launch_bounds__(256)
void means_prep_kernel(const float* __restrict__ h,
                       const float* __restrict__ primitives_state,
                       const float* __restrict__ hebbian_traces,
                       const float* __restrict__ decay_logit,
                       const float* __restrict__ msg_magnitude,
                       const float* __restrict__ sw1,
                       const float* __restrict__ mw1,
                       const float* __restrict__ sw2,
                       const float* __restrict__ mw2)
{
    const int tid = threadIdx.x;

    if (blockIdx.x >= MEANS_BLOCKS) {
        int pt = (blockIdx.x - MEANS_BLOCKS) * 256 + tid;
        if (pt < 12288) {
            int i4 = pt >> 8, hh = pt & 255;
            float4 v = make_float4(sw1[hh * 193 + i4 * 4 + 0], sw1[hh * 193 + i4 * 4 + 1],
                                   sw1[hh * 193 + i4 * 4 + 2], sw1[hh * 193 + i4 * 4 + 3]);
            *(float4*)&g_sw1T4[pt * 4] = v;
        } else if (pt < 24576) {
            int q = pt - 12288, i4 = q >> 8, hh = q & 255;
            float4 v = make_float4(mw1[hh * 192 + i4 * 4 + 0], mw1[hh * 192 + i4 * 4 + 1],
                                   mw1[hh * 192 + i4 * 4 + 2], mw1[hh * 192 + i4 * 4 + 3]);
            *(float4*)&g_mw1T4[q * 4] = v;
        } else if (pt < 28672) {
            int q = pt - 24576, h4 = q >> 6, d = q & 63;
            float4 v = make_float4(sw2[d * 256 + h4 * 4 + 0], sw2[d * 256 + h4 * 4 + 1],
                                   sw2[d * 256 + h4 * 4 + 2], sw2[d * 256 + h4 * 4 + 3]);
            *(float4*)&g_sw2T4[q * 4] = v;
        } else if (pt < 32768) {
            int q = pt - 28672, h4 = q >> 6, d = q & 63;
            float4 v = make_float4(mw2[d * 256 + h4 * 4 + 0], mw2[d * 256 + h4 * 4 + 1],
                                   mw2[d * 256 + h4 * 4 + 2], mw2[d * 256 + h4 * 4 + 3]);
            *(float4*)&g_mw2T4[q * 4] = v;
        } else if (pt < 33024) {
            int hh = pt - 32768;
            g_sw1last[hh] = sw1[hh * 193 + 192];
        }
        return;
    }

    __shared__ float s_h[1024];
    __shared__ float s_p[1024];
    __shared__ float s_b[1024];

    const int bn   = blockIdx.x >> 1;
    const int half = blockIdx.x & 1;
    const int c0   = half * 128;
    const int lane = tid & 31;
    const int warp = tid >> 5;
    const int pidx = blockIdx.x;

    const float4* hp4 = (const float4*)(h                + (long)bn * CDIM * DDIM + (long)c0 * DDIM);
    const float4* pp4 = (const float4*)(primitives_state + (long)bn * CDIM * DDIM + (long)c0 * DDIM);
    const float4* hb4 = (const float4*)(hebbian_traces   + (long)bn * CDIM * KDIM + (long)c0 * KDIM);

    const int v16 = tid & 15;
    const int cgr = tid >> 4;
    const int v8  = tid & 7;
    const int cb  = tid >> 3;

    float4 ha[8], pa[8], ba[4];
    #pragma unroll
    for (int j = 0; j < 8; j++) ha[j] = hp4[(cgr + 16 * j) * 16 + v16];
    #pragma unroll
    for (int j = 0; j < 8; j++) pa[j] = pp4[(cgr + 16 * j) * 16 + v16];
    #pragma unroll
    for (int j = 0; j < 4; j++) ba[j] = hb4[(cb + 32 * j) * 8 + v8];

    if (warp == 0) {
        const float* dl = decay_logit + (long)bn * CDIM + c0;
        float v = dl[lane] + dl[lane + 32] + dl[lane + 64] + dl[lane + 96];
        #pragma unroll
        for (int off = 16; off; off >>= 1) v += __shfl_down_sync(0xffffffffu, v, off);
        if (lane == 0) g_pd[pidx] = v;
    } else if (warp == 1) {
        const float* mg = msg_magnitude + (long)bn * CDIM + c0;
        float v = mg[lane] + mg[lane + 32] + mg[lane + 64] + mg[lane + 96];
        #pragma unroll
        for (int off = 16; off; off >>= 1) v += __shfl_down_sync(0xffffffffu, v, off);
        if (lane == 0) g_pmg[pidx] = v;
    }

    float4 hs, ps, bs;
    hs.x = ((ha[0].x + ha[1].x) + (ha[2].x + ha[3].x)) + ((ha[4].x + ha[5].x) + (ha[6].x + ha[7].x));
    hs.y = ((ha[0].y + ha[1].y) + (ha[2].y + ha[3].y)) + ((ha[4].y + ha[5].y) + (ha[6].y + ha[7].y));
    hs.z = ((ha[0].z + ha[1].z) + (ha[2].z + ha[3].z)) + ((ha[4].z + ha[5].z) + (ha[6].z + ha[7].z));
    hs.w = ((ha[0].w + ha[1].w) + (ha[2].w + ha[3].w)) + ((ha[4].w + ha[5].w) + (ha[6].w + ha[7].w));
    ps.x = ((pa[0].x + pa[1].x) + (pa[2].x + pa[3].x)) + ((pa[4].x + pa[5].x) + (pa[6].x + pa[7].x));
    ps.y = ((pa[0].y + pa[1].y) + (pa[2].y + pa[3].y)) + ((pa[4].y + pa[5].y) + (pa[6].y + pa[7].y));
    ps.z = ((pa[0].z + pa[1].z) + (pa[2].z + pa[3].z)) + ((pa[4].z + pa[5].z) + (pa[6].z + pa[7].z));
    ps.w = ((pa[0].w + pa[1].w) + (pa[2].w + pa[3].w)) + ((pa[4].w + pa[5].w) + (pa[6].w + pa[7].w));
    bs.x = (ba[0].x + ba[1].x) + (ba[2].x + ba[3].x);
    bs.y = (ba[0].y + ba[1].y) + (ba[2].y + ba[3].y);
    bs.z = (ba[0].z + ba[1].z) + (ba[2].z + ba[3].z);
    bs.w = (ba[0].w + ba[1].w) + (ba[2].w + ba[3].w);

    *(float4*)&s_h[cgr * 64 + v16 * 4] = hs;
    *(float4*)&s_p[cgr * 64 + v16 * 4] = ps;
    *(float4*)&s_b[cb * 32 + v8 * 4]   = bs;
    __syncthreads();

    if (tid < 64) {
        float t = 0.f;
        #pragma unroll
        for (int g = 0; g < 16; g++) t += s_h[g * 64 + tid];
        g_ph[pidx * 64 + tid] = t;
    } else if (tid < 128) {
        int d = tid - 64;
        float t = 0.f;
        #pragma unroll
        for (int g = 0; g < 16; g++) t += s_p[g * 64 + d];
        g_pp[pidx * 64 + d] = t;
    } else if (tid < 160) {
        int k = tid - 128;
        float t = 0.f;
        #pragma unroll
        for (int c2 = 0; c2 < 32; c2++) t += s_b[c2 * 32 + k];
        g_phb[pidx * 32 + k] = t;
    }
}

// ---------------- K2 (unchanged; PDL on K1) ----------------
__global__ __launch_bounds__(256)
void modmlp_kernel(const float* __restrict__ mod_w1,
                   const float* __restrict__ mod_b1,
                   const float* __restrict__ mod_w2,
                   const float* __restrict__ mod_b2,
                   const float* __restrict__ neuron_id)
{
    __shared__ float s_min[2][232];
    __shared__ float s_hid[2][64];
    __shared__ float s_mm[2];
    __shared__ __align__(16) float s_nid[8][64];
    __shared__ float s_ps[4][512];
    __shared__ float s_pm[4][512];

    const int tid  = threadIdx.x;
    const int warp = tid >> 5;
    const int lane = tid & 31;
    const int nc   = blockIdx.x & 63;
    const int q    = (blockIdx.x >> 6) & 3;
    const int bp   = blockIdx.x >> 8;
    const float inv = 1.0f / CDIM;

    if (bp == 0) {
        int c = tid >> 5, d0 = (tid & 31) * 2;
        *(float2*)&s_nid[c][d0] = *(const float2*)&neuron_id[((long)nc * CDIM + (CDIM - ALPHA) + c) * DDIM + d0];
    }

    cudaGridDependencySynchronize();

    {
        int b2 = tid >> 7, r = tid & 127;
        int b  = bp * 2 + b2;
        int p0 = ((b * NCB + nc) << 1);
        if (r < 64) {
            s_min[b2][32 + r] = (g_ph[p0 * 64 + r] + g_ph[(p0 + 1) * 64 + r]) * inv;
        } else {
            int d = r - 64;
            s_min[b2][97 + d] = (g_pp[p0 * 64 + d] + g_pp[(p0 + 1) * 64 + d]) * inv;
        }
        if (tid < 64) {
            int bb = tid >> 5, k = tid & 31;
            int p = (((bp * 2 + bb) * NCB + nc) << 1);
            s_min[bb][k] = (g_phb[p * 32 + k] + g_phb[(p + 1) * 32 + k]) * inv;
        } else if (tid < 66) {
            int bb = tid - 64;
            int p = (((bp * 2 + bb) * NCB + nc) << 1);
            s_min[bb][96] = (g_pd[p] + g_pd[p + 1]) * inv;
        } else if (tid < 68) {
            int bb = tid - 66;
            int p = (((bp * 2 + bb) * NCB + nc) << 1);
            s_mm[bb] = (g_pmg[p] + g_pmg[p + 1]) * inv;
        }
    }
    __syncthreads();
    {
        int b2 = tid >> 7, r = tid & 127;
        if (r < 64) s_min[b2][161 + r] = s_mm[b2];
    }
    __syncthreads();

    if (bp == 0) {
        int hhl = tid & 63, ig = tid >> 6;
        int hh = q * 64 + hhl;
        float accs[8], accm[8];
        #pragma unroll
        for (int c = 0; c < 8; c++) { accs[c] = 0.f; accm[c] = 0.f; }
        #pragma unroll
        for (int s = 0; s < 4; s++) {
            int i4 = 32 + ig * 4 + s;
            int i  = (i4 - 32) * 4;
            float4 ws = *(const float4*)&g_sw1T4[(i4 * 256 + hh) * 4];
            float4 wm = *(const float4*)&g_mw1T4[(i4 * 256 + hh) * 4];
            #pragma unroll
            for (int c = 0; c < 8; c++) {
                float4 nv = *(const float4*)&s_nid[c][i];
                accs[c] += nv.x * ws.x + nv.y * ws.y + nv.z * ws.z + nv.w * ws.w;
                accm[c] += nv.x * wm.x + nv.y * wm.y + nv.z * wm.z + nv.w * wm.w;
            }
        }
        #pragma unroll
        for (int c = 0; c < 8; c++) {
            s_ps[ig][hhl * 8 + c] = accs[c];
            s_pm[ig][hhl * 8 + c] = accm[c];
        }
        __syncthreads();
        for (int o = tid; o < 512; o += 256) {
            int hhl2 = o >> 3;
            int hh2 = q * 64 + hhl2;
            int c = o & 7;
            g_ndot_s[((long)nc * 256 + hh2) * 8 + c] = s_ps[0][o] + s_ps[1][o] + s_ps[2][o] + s_ps[3][o];
            g_ndot_m[((long)nc * 256 + hh2) * 8 + c] = s_pm[0][o] + s_pm[1][o] + s_pm[2][o] + s_pm[3][o];
        }
    }

    for (int r = 0; r < 8; r++) {
        int rloc = warp * 8 + r;
        int h0 = q * 64 + rloc;
        const float* row = mod_w1 + ((long)nc * HDIM + h0) * MODI;
        float a0 = 0.f, a1 = 0.f;
        #pragma unroll
        for (int j = 0; j < 7; j++) {
            int i = lane + 32 * j;
            float w = row[i];
            a0 += w * s_min[0][i];
            a1 += w * s_min[1][i];
        }
        if (lane == 0) {
            float w = row[224];
            a0 += w * s_min[0][224];
            a1 += w * s_min[1][224];
        }
        #pragma unroll
        for (int off = 16; off; off >>= 1) {
            a0 += __shfl_down_sync(0xffffffffu, a0, off);
            a1 += __shfl_down_sync(0xffffffffu, a1, off);
        }
        if (lane == 0) {
            float bias = mod_b1[nc * HDIM + h0];
            s_hid[0][rloc] = ftanh(a0 + bias);
            s_hid[1][rloc] = ftanh(a1 + bias);
        }
    }
    __syncthreads();

    if (tid < 194) {
        int o = tid >> 1, bl = tid & 1;
        int b = bp * 2 + bl;
        const float* w2c = mod_w2 + (long)nc * HDIM * MODO + (long)(q * 64) * MODO + o;
        float a = 0.f;
        #pragma unroll 8
        for (int hh = 0; hh < 64; hh++) a += w2c[hh * MODO] * s_hid[bl][hh];
        if (q == 0) a += mod_b2[nc * MODO + o];
        g_l2p[(((long)b * NCB + nc) * 4 + q) * 100 + o] = a;
    }
}

// ---------------- K3: 256 threads, full-i per thread, 3 blocks/SM; PDL on K2 ----------------
__global__ __launch_bounds__(256, 3)
void cellmem_kernel(
    const float* __restrict__ h,
    const float* __restrict__ prev_messages,
    const float* __restrict__ state_b1,
    const float* __restrict__ state_b2,
    const float* __restrict__ msg_b1,
    const float* __restrict__ msg_b2,
    const int*   __restrict__ conn_indices,
    float* __restrict__ out)
{
    __shared__ float s_wsig[32];
    __shared__ __align__(16) float s_prim[64];
    __shared__ float s_scal[2];
    __shared__ int   s_conn[256];
    __shared__ __align__(16) float s_hvT[512];     // [d][c]
    __shared__ __align__(16) float s_invT[512];    // [d][c]
    __shared__ __align__(16) float s_hnewT[512];   // [d][c]
    __shared__ __align__(16) float s_scratch[2048];// [hq][d][c]  4*64*8
    __shared__ __align__(16) float s_t[2048];      // [hh][c]
    __shared__ __align__(16) float s_acc8T[512];   // [d][c]

    const int tid  = threadIdx.x;
    const int warp = tid >> 5;
    const int lane = tid & 31;
    const int b    = blockIdx.x >> 6;
    const int nc   = blockIdx.x & 63;
    const long bn  = (long)b * NCB + nc;

    const float* hp = h             + bn * CDIM * DDIM;
    const float* pm = prev_messages + bn * CDIM * DDIM;

    // ---- PDL prologue: inputs only (conn, h) ----
    {
        int cc = tid >> 5, k = tid & 31;
        s_conn[tid] = conn_indices[((long)nc * CDIM + (CDIM - ALPHA) + cc) * KDIM + k];
    }
    #pragma unroll
    for (int r = 0; r < 2; r++) {
        int idx = tid + 256 * r;
        int c = idx >> 6, d = idx & 63;
        s_hvT[d * 8 + c] = hp[((CDIM - ALPHA) + c) * DDIM + d];
    }

    cudaGridDependencySynchronize();

    // ---------- P1 ----------
    if (tid < MODO) {
        float v = g_l2p[(bn * 4 + 0) * 100 + tid] + g_l2p[(bn * 4 + 1) * 100 + tid]
                + g_l2p[(bn * 4 + 2) * 100 + tid] + g_l2p[(bn * 4 + 3) * 100 + tid];
        if (tid < KDIM)        s_wsig[tid] = sigm(v);
        else if (tid == KDIM) { s_scal[0] = v; s_scal[1] = sigm(v); }
        else                   s_prim[tid - KDIM - 1] = v;
    }
    __syncthreads();

    // ---------- P5: gather (warp per cell, all 32 k) ----------
    {
        int cc = warp;
        float ax = 0.f, ay = 0.f, bx = 0.f, by = 0.f;
        #pragma unroll 4
        for (int k = 0; k < KDIM; k += 2) {
            const float2* p0 = (const float2*)(pm + (long)s_conn[cc * KDIM + k] * DDIM);
            const float2* p1 = (const float2*)(pm + (long)s_conn[cc * KDIM + k + 1] * DDIM);
            float w0 = s_wsig[k], w1 = s_wsig[k + 1];
            float2 v0 = p0[lane], v1 = p1[lane];
            ax += w0 * v0.x; ay += w0 * v0.y;
            bx += w1 * v1.x; by += w1 * v1.y;
        }
        s_invT[(lane * 2) * 8 + cc]     = ax + bx;
        s_invT[(lane * 2 + 1) * 8 + cc] = ay + by;
    }
    __syncthreads();

    // ---------- P6: state hidden (thread = hh, full i range) ----------
    {
        int hh = tid;
        unsigned long long acc2[4];
        {
            const ulonglong2* np = (const ulonglong2*)&g_ndot_s[((long)nc * 256 + hh) * 8];
            ulonglong2 n01 = np[0], n23 = np[1];
            acc2[0] = n01.x; acc2[1] = n01.y; acc2[2] = n23.x; acc2[3] = n23.y;
        }
        float pdot = 0.f;
        #pragma unroll
        for (int i4 = 0; i4 < 16; i4++) {
            int i = i4 * 4;
            float wa[4], wb[4];
            *(float4*)wa = *(const float4*)&g_sw1T4[(i4 * 256 + hh) * 4];
            *(float4*)wb = *(const float4*)&g_sw1T4[((i4 + 16) * 256 + hh) * 4];
            float4 pv = *(const float4*)&s_prim[i];
            pdot += pv.x * wb[0] + pv.y * wb[1] + pv.z * wb[2] + pv.w * wb[3];
            #pragma unroll
            for (int e = 0; e < 4; e++) {
                unsigned long long w2 = pk(wa[e], wa[e]);
                const ulonglong2* ivp = (const ulonglong2*)&s_invT[(i + e) * 8];
                ulonglong2 p01 = ivp[0], p23 = ivp[1];
                acc2[0] = ffma2u(w2, p01.x, acc2[0]);
                acc2[1] = ffma2u(w2, p01.y, acc2[1]);
                acc2[2] = ffma2u(w2, p23.x, acc2[2]);
                acc2[3] = ffma2u(w2, p23.y, acc2[3]);
            }
        }
        float extra = pdot + state_b1[hh] + s_scal[0] * g_sw1last[hh];
        #pragma unroll
        for (int j = 0; j < 4; j++) {
            float2 r = upk(acc2[j]);
            s_t[hh * 8 + 2 * j]     = ftanh(r.x + extra);
            s_t[hh * 8 + 2 * j + 1] = ftanh(r.y + extra);
        }
    }
    __syncthreads();

    // ---------- P7: update + h_new (thread = (d, hq), 4-way hq split) ----------
    {
        int d = tid & 63, hq = tid >> 6;
        unsigned long long z = pk(0.f, 0.f);
        unsigned long long acc2[4] = {z, z, z, z};
        #pragma unroll
        for (int s = 0; s < 16; s++) {
            int h4 = hq * 16 + s, hh = h4 * 4;
            float wa[4];
            *(float4*)wa = *(const float4*)&g_sw2T4[(h4 * 64 + d) * 4];
            #pragma unroll
            for (int e = 0; e < 4; e++) {
                unsigned long long w2 = pk(wa[e], wa[e]);
                const ulonglong2* tp = (const ulonglong2*)&s_t[(hh + e) * 8];
                ulonglong2 p01 = tp[0], p23 = tp[1];
                acc2[0] = ffma2u(w2, p01.x, acc2[0]);
                acc2[1] = ffma2u(w2, p01.y, acc2[1]);
                acc2[2] = ffma2u(w2, p23.x, acc2[2]);
                acc2[3] = ffma2u(w2, p23.y, acc2[3]);
            }
        }
        ulonglong2* op = (ulonglong2*)&s_scratch[hq * 512 + d * 8];
        op[0] = make_ulonglong2(acc2[0], acc2[1]);
        op[1] = make_ulonglong2(acc2[2], acc2[3]);
    }
    __syncthreads();
    {
        float ds = s_scal[1];
        #pragma unroll
        for (int r = 0; r < 2; r++) {
            int idx = tid + 256 * r;
            int d = idx >> 3;
            float a = s_scratch[idx] + s_scratch[512 + idx] + s_scratch[1024 + idx] + s_scratch[1536 + idx]
                    + state_b2[d];
            s_hnewT[idx] = ds * s_hvT[idx] + (1.f - ds) * ftanh(a);
        }
    }
    __syncthreads();

    // ---------- P8: msg hidden (thread = hh, full i range) ----------
    {
        int hh = tid;
        unsigned long long acc2[4];
        {
            const ulonglong2* np = (const ulonglong2*)&g_ndot_m[((long)nc * 256 + hh) * 8];
            ulonglong2 n01 = np[0], n23 = np[1];
            acc2[0] = n01.x; acc2[1] = n01.y; acc2[2] = n23.x; acc2[3] = n23.y;
        }
        float pdot = 0.f;
        #pragma unroll
        for (int i4 = 0; i4 < 16; i4++) {
            int i = i4 * 4;
            float wa[4], wb[4];
            *(float4*)wa = *(const float4*)&g_mw1T4[(i4 * 256 + hh) * 4];
            *(float4*)wb = *(const float4*)&g_mw1T4[((i4 + 16) * 256 + hh) * 4];
            float4 pv = *(const float4*)&s_prim[i];
            pdot += pv.x * wb[0] + pv.y * wb[1] + pv.z * wb[2] + pv.w * wb[3];
            #pragma unroll
            for (int e = 0; e < 4; e++) {
                unsigned long long w2 = pk(wa[e], wa[e]);
                const ulonglong2* ivp = (const ulonglong2*)&s_hnewT[(i + e) * 8];
                ulonglong2 p01 = ivp[0], p23 = ivp[1];
                acc2[0] = ffma2u(w2, p01.x, acc2[0]);
                acc2[1] = ffma2u(w2, p01.y, acc2[1]);
                acc2[2] = ffma2u(w2, p23.x, acc2[2]);
                acc2[3] = ffma2u(w2, p23.y, acc2[3]);
            }
        }
        float extra = pdot + msg_b1[hh];
        #pragma unroll
        for (int j = 0; j < 4; j++) {
            float2 r = upk(acc2[j]);
            s_t[hh * 8 + 2 * j]     = ftanh(r.x + extra);
            s_t[hh * 8 + 2 * j + 1] = ftanh(r.y + extra);
        }
    }
    __syncthreads();

    // ---------- P9: msg out + readout ----------
    {
        int d = tid & 63, hq = tid >> 6;
        unsigned long long z = pk(0.f, 0.f);
        unsigned long long acc2[4] = {z, z, z, z};
        #pragma unroll
        for (int s = 0; s < 16; s++) {
            int h4 = hq * 16 + s, hh = h4 * 4;
            float wa[4];
            *(float4*)wa = *(const float4*)&g_mw2T4[(h4 * 64 + d) * 4];
            #pragma unroll
            for (int e = 0; e < 4; e++) {
                unsigned long long w2 = pk(wa[e], wa[e]);
                const ulonglong2* tp = (const ulonglong2*)&s_t[(hh + e) * 8];
                ulonglong2 p01 = tp[0], p23 = tp[1];
                acc2[0] = ffma2u(w2, p01.x, acc2[0]);
                acc2[1] = ffma2u(w2, p01.y, acc2[1]);
                acc2[2] = ffma2u(w2, p23.x, acc2[2]);
                acc2[3] = ffma2u(w2, p23.y, acc2[3]);
            }
        }
        ulonglong2* op = (ulonglong2*)&s_scratch[hq * 512 + d * 8];
        op[0] = make_ulonglong2(acc2[0], acc2[1]);
        op[1] = make_ulonglong2(acc2[2], acc2[3]);
    }
    __syncthreads();
    {
        #pragma unroll
        for (int r = 0; r < 2; r++) {
            int idx = tid + 256 * r;
            int d = idx >> 3;
            float a = s_scratch[idx] + s_scratch[512 + idx] + s_scratch[1024 + idx] + s_scratch[1536 + idx]
                    + msg_b2[d];
            s_acc8T[idx] = ftanh(a);
        }
    }
    __syncthreads();
    if (tid < 64) {
        float4 a0 = *(const float4*)&s_acc8T[tid * 8];
        float4 a1 = *(const float4*)&s_acc8T[tid * 8 + 4];
        out[(long)b * (NCB * DDIM) + nc * DDIM + tid] =
            ((a0.x + a0.y) + (a0.z + a0.w) + (a1.x + a1.y) + (a1.z + a1.w)) * 0.125f;
    }
}

extern "C" void kernel_launch(void* const* d_in, const int* in_sizes, int n_in,
                              void* d_out, int out_size)
{
    const float* h          = (const float*)d_in[0];
    const float* prev_msg   = (const float*)d_in[1];
    const float* decay      = (const float*)d_in[2];
    const float* prim       = (const float*)d_in[3];
    const float* hebb       = (const float*)d_in[4];
    const float* msgmag     = (const float*)d_in[5];
    // d_in[6] = cc_signals : dead
    const float* state_w1   = (const float*)d_in[7];
    const float* state_b1   = (const float*)d_in[8];
    const float* state_w2   = (const float*)d_in[9];
    const float* state_b2   = (const float*)d_in[10];
    const float* msg_w1     = (const float*)d_in[11];
    const float* msg_b1     = (const float*)d_in[12];
    const float* msg_w2     = (const float*)d_in[13];
    const float* msg_b2     = (const float*)d_in[14];
    const float* mod_w1     = (const float*)d_in[15];
    const float* mod_b1     = (const float*)d_in[16];
    const float* mod_w2     = (const float*)d_in[17];
    const float* mod_b2     = (const float*)d_in[18];
    const float* neuron_id  = (const float*)d_in[19];
    const int*   conn       = (const int*)d_in[20];
    float* outp             = (float*)d_out;

    means_prep_kernel<<<MEANS_BLOCKS + PREP_BLOCKS, 256>>>(
        h, prim, hebb, decay, msgmag, state_w1, msg_w1, state_w2, msg_w2);

    {
        cudaLaunchConfig_t cfg = {};
        cfg.gridDim  = dim3(512, 1, 1);
        cfg.blockDim = dim3(256, 1, 1);
        cudaLaunchAttribute attrs[1];
        attrs[0].id = cudaLaunchAttributeProgrammaticStreamSerialization;
        attrs[0].val.programmaticStreamSerializationAllowed = 1;
        cfg.attrs = attrs;
        cfg.numAttrs = 1;
        cudaLaunchKernelEx(&cfg, modmlp_kernel, mod_w1, mod_b1, mod_w2, mod_b2, neuron_id);
    }

    {
        cudaLaunchConfig_t cfg = {};
        cfg.gridDim  = dim3(256, 1, 1);
        cfg.blockDim = dim3(256, 1, 1);
        cudaLaunchAttribute attrs[1];
        attrs[0].id = cudaLaunchAttributeProgrammaticStreamSerialization;
        attrs[0].val.programmaticStreamSerializationAllowed = 1;
        cfg.attrs = attrs;
        cfg.numAttrs = 1;
        cudaLaunchKernelEx(&cfg, cellmem_kernel, h, prev_msg,
                           state_b1, state_b2, msg_b1, msg_b2, conn, outp);
    }
}